// round 1
// baseline (speedup 1.0000x reference)
#include <cuda_runtime.h>

#define Bb 96
#define Tt 48
#define LD 64
#define GD 64
#define MT 10
#define HH 128

#define NT 256
#define SW_F 16384
#define SH1_STRIDE 129
#define SH1_F (Bb*SH1_STRIDE)

typedef unsigned long long ull;

// Scratch (device globals: no allocation allowed)
__device__ float g_A[Bb*Tt*HH];   // locals @ lw1[:64]          [4608,128]
__device__ float g_Bg[Bb*HH];     // globals @ lw1[64:] + lb1   [96,128]
__device__ float g_P[Bb*HH];      // sampled-locals @ gw1[:640] [96,128]
__device__ float g_Q[Bb*HH];      // globals @ gw1[640:] + gb1  [96,128]

__device__ __forceinline__ ull pack2(float lo, float hi){
    ull r; asm("mov.b64 %0, {%1, %2};" : "=l"(r) : "f"(lo), "f"(hi)); return r;
}
__device__ __forceinline__ void fma2(ull &d, ull a, ull b){
    asm("fma.rn.f32x2 %0, %1, %2, %0;" : "+l"(d) : "l"(a), "l"(b));
}
__device__ __forceinline__ float2 unpack2(ull v){
    float2 f; asm("mov.b64 {%0, %1}, %2;" : "=f"(f.x), "=f"(f.y) : "l"(v)); return f;
}

// ---------------------------------------------------------------------------
// Precompute: per batch-row i, compute A (48 rows), Bg, P, Q.
// ---------------------------------------------------------------------------
__global__ __launch_bounds__(128) void precompute_kernel(
    const float* __restrict__ globals_, const float* __restrict__ locals_,
    const float* __restrict__ gw1, const float* __restrict__ gb1,
    const float* __restrict__ lw1, const float* __restrict__ lb1,
    const int* __restrict__ idx_t)
{
    __shared__ float ltile[Tt*LD];     // 12 KB
    __shared__ float lsrow[MT*LD];     // 2.5 KB
    __shared__ float grow[GD];
    __shared__ int   sidx[MT];

    const int i = blockIdx.x;
    const int tid = threadIdx.x;

    for (int idx = tid; idx < Tt*LD; idx += 128) ltile[idx] = locals_[i*Tt*LD + idx];
    if (tid < GD) grow[tid] = globals_[i*GD + tid];
    if (tid < MT) sidx[tid] = idx_t[i*MT + tid];
    __syncthreads();
    for (int idx = tid; idx < MT*LD; idx += 128) {
        int m = idx >> 6, k = idx & 63;
        lsrow[idx] = ltile[sidx[m]*LD + k];
    }
    __syncthreads();

    const int h = tid;  // 128 threads = 128 output features

    // A[i*48+t][h] = locals[i,t,:] @ lw1[0:64, h]
    float acc[Tt];
    #pragma unroll
    for (int t = 0; t < Tt; t++) acc[t] = 0.f;
    for (int k = 0; k < LD; k++) {
        float w = lw1[k*HH + h];
        #pragma unroll
        for (int t = 0; t < Tt; t++) acc[t] += ltile[t*LD + k] * w;
    }
    #pragma unroll
    for (int t = 0; t < Tt; t++) g_A[(i*Tt + t)*HH + h] = acc[t];

    // Bg[i][h] = globals[i] @ lw1[64:, h] + lb1[h]
    float bv = lb1[h];
    for (int k = 0; k < GD; k++) bv += grow[k] * lw1[(LD + k)*HH + h];
    g_Bg[i*HH + h] = bv;

    // Q[i][h] = globals[i] @ gw1[640:, h] + gb1[h]
    float qv = gb1[h];
    for (int k = 0; k < GD; k++) qv += grow[k] * gw1[(MT*LD + k)*HH + h];
    g_Q[i*HH + h] = qv;

    // P[i][h] = lsrow @ gw1[0:640, h]
    float pv = 0.f;
    for (int k = 0; k < MT*LD; k++) pv += lsrow[k] * gw1[k*HH + h];
    g_P[i*HH + h] = pv;
}

// ---------------------------------------------------------------------------
// MI kernel: for each row r (a precomputed layer-1 left operand) and all 96 j:
//   h1 = relu(arow + brows[j]);  h2 = relu(h1 @ w2 + b2);  out = h2 . w3 + b3
// 256 threads: 16 j-groups (6 j each) x 16 h-groups (8 h each = 4+4 split).
// f32x2 packed FMA accumulators (24 per thread).
// ---------------------------------------------------------------------------
__global__ __launch_bounds__(NT, 1) void mi_kernel(
    const float* __restrict__ w2, const float* __restrict__ b2,
    const float* __restrict__ w3, const float* __restrict__ b3,
    float* __restrict__ out, int nrows, int iters, int is_local)
{
    extern __shared__ float sm[];
    float* sw    = sm;                 // [128][128] w2, 64 KB
    float* sh1   = sm + SW_F;          // [96][129]  h1 tile
    float* sarow = sh1 + SH1_F;        // [128]
    float* sw3   = sarow + HH;         // [128]

    const float* arows = is_local ? g_A  : g_P;
    const float* brows = is_local ? g_Bg : g_Q;

    const int tid = threadIdx.x;
    const int jg = tid >> 4;           // 0..15  (2 per warp)
    const int hg = tid & 15;           // 0..15
    const int hA = hg * 4;
    const int hB = 64 + hg * 4;
    const int jb = jg * 6;

    // Load w2, w3 into smem
    const float4* w24 = (const float4*)w2;
    float4* sw4 = (float4*)sw;
    for (int idx = tid; idx < SW_F/4; idx += NT) sw4[idx] = w24[idx];
    if (tid < HH) sw3[tid] = w3[tid];

    // b2 accumulator init (pairs), b3
    float2 q0 = *(const float2*)(b2 + hA);
    float2 q1 = *(const float2*)(b2 + hA + 2);
    float2 q2 = *(const float2*)(b2 + hB);
    float2 q3 = *(const float2*)(b2 + hB + 2);
    ull binit[4] = { pack2(q0.x,q0.y), pack2(q1.x,q1.y), pack2(q2.x,q2.y), pack2(q3.x,q3.y) };
    const float b3v = b3[0];

    for (int r = 0; r < iters; r++) {
        const int row = blockIdx.x * iters + r;
        if (row >= nrows) break;

        __syncthreads();   // prior iter done reading sh1/sarow; first iter: orders sw loads
        if (tid < HH) sarow[tid] = arows[row*HH + tid];
        __syncthreads();

        // h1[j][k] = relu(arow[k] + brows[j][k])
        for (int idx = tid; idx < Bb*HH; idx += NT) {
            int k = idx & 127;
            float v = sarow[k] + brows[idx];
            sh1[(idx >> 7)*SH1_STRIDE + k] = v > 0.f ? v : 0.f;
        }
        __syncthreads();

        ull acc[6][4];
        #pragma unroll
        for (int jj = 0; jj < 6; jj++) {
            #pragma unroll
            for (int p = 0; p < 4; p++) acc[jj][p] = binit[p];
        }

        #pragma unroll 4
        for (int k = 0; k < HH; k++) {
            float4 wa = sw4[(k << 5) + hg];        // w2[k][hA..hA+3]
            float4 wb = sw4[(k << 5) + 16 + hg];   // w2[k][hB..hB+3]
            ull bf0 = pack2(wa.x, wa.y), bf1 = pack2(wa.z, wa.w);
            ull bf2 = pack2(wb.x, wb.y), bf3 = pack2(wb.z, wb.w);
            #pragma unroll
            for (int jj = 0; jj < 6; jj++) {
                float a = sh1[(jb + jj)*SH1_STRIDE + k];
                ull a2 = pack2(a, a);
                fma2(acc[jj][0], a2, bf0);
                fma2(acc[jj][1], a2, bf1);
                fma2(acc[jj][2], a2, bf2);
                fma2(acc[jj][3], a2, bf3);
            }
        }

        // Epilogue: relu(h2) . w3, reduce over 16 hg lanes
        #pragma unroll
        for (int jj = 0; jj < 6; jj++) {
            float2 v0 = unpack2(acc[jj][0]);
            float2 v1 = unpack2(acc[jj][1]);
            float2 v2 = unpack2(acc[jj][2]);
            float2 v3 = unpack2(acc[jj][3]);
            float s = fmaxf(v0.x,0.f)*sw3[hA]   + fmaxf(v0.y,0.f)*sw3[hA+1]
                    + fmaxf(v1.x,0.f)*sw3[hA+2] + fmaxf(v1.y,0.f)*sw3[hA+3]
                    + fmaxf(v2.x,0.f)*sw3[hB]   + fmaxf(v2.y,0.f)*sw3[hB+1]
                    + fmaxf(v3.x,0.f)*sw3[hB+2] + fmaxf(v3.y,0.f)*sw3[hB+3];
            s += __shfl_xor_sync(0xffffffffu, s, 1);
            s += __shfl_xor_sync(0xffffffffu, s, 2);
            s += __shfl_xor_sync(0xffffffffu, s, 4);
            s += __shfl_xor_sync(0xffffffffu, s, 8);
            if (hg == 0) {
                int j = jb + jj;
                int o;
                if (is_local) {
                    int ii = row / Tt, tt = row - ii*Tt;
                    o = tt*(Bb*Bb) + ii*Bb + j;      // locals_mi[t][i][j]
                } else {
                    o = row*Bb + j;                   // globals_mi[i][j]
                }
                out[o] = s + b3v;
            }
        }
    }
}

// ---------------------------------------------------------------------------
extern "C" void kernel_launch(void* const* d_in, const int* in_sizes, int n_in,
                              void* d_out, int out_size)
{
    const float* globals_ = (const float*)d_in[0];
    const float* locals_  = (const float*)d_in[1];
    const float* gw1 = (const float*)d_in[2];
    const float* gb1 = (const float*)d_in[3];
    const float* gw2 = (const float*)d_in[4];
    const float* gb2 = (const float*)d_in[5];
    const float* gw3 = (const float*)d_in[6];
    const float* gb3 = (const float*)d_in[7];
    const float* lw1 = (const float*)d_in[8];
    const float* lb1 = (const float*)d_in[9];
    const float* lw2 = (const float*)d_in[10];
    const float* lb2 = (const float*)d_in[11];
    const float* lw3 = (const float*)d_in[12];
    const float* lb3 = (const float*)d_in[13];
    const int*  idx_t = (const int*)d_in[14];

    float* out = (float*)d_out;

    // Pass-through outputs
    cudaMemcpyAsync(out, globals_, (size_t)Bb*GD*sizeof(float),
                    cudaMemcpyDeviceToDevice, 0);
    cudaMemcpyAsync(out + Bb*GD, locals_, (size_t)Bb*Tt*LD*sizeof(float),
                    cudaMemcpyDeviceToDevice, 0);

    precompute_kernel<<<Bb, 128>>>(globals_, locals_, gw1, gb1, lw1, lb1, idx_t);

    size_t smem = (size_t)(SW_F + SH1_F + HH + HH) * sizeof(float);
    cudaFuncSetAttribute(mi_kernel, cudaFuncAttributeMaxDynamicSharedMemorySize, (int)smem);

    float* gmi = out + (Bb*GD + Bb*Tt*LD);
    float* lmi = gmi + Bb*Bb;

    // locals path: 4608 rows, 8 rows per CTA (w2 stays resident in smem)
    mi_kernel<<<(Bb*Tt)/8, NT, smem>>>(lw2, lb2, lw3, lb3, lmi, Bb*Tt, 8, 1);
    // globals path: 96 rows
    mi_kernel<<<Bb, NT, smem>>>(gw2, gb2, gw3, gb3, gmi, Bb, 1, 0);
}

// round 7
// speedup vs baseline: 1.0234x; 1.0234x over previous
#include <cuda_runtime.h>

#define Bb 96
#define Tt 48
#define LD 64
#define GD 64
#define MT 10
#define HH 128

#define NT 256
#define SW_F 16384
#define SH1_STRIDE 129
#define SH1_F (Bb*SH1_STRIDE)

typedef unsigned long long ull;

// Scratch (device globals: no allocation allowed)
__device__ float g_A[Bb*Tt*HH];   // locals @ lw1[:64]          [4608,128]
__device__ float g_Bg[Bb*HH];     // globals @ lw1[64:] + lb1   [96,128]
__device__ float g_P[Bb*HH];      // sampled-locals @ gw1[:640] [96,128]
__device__ float g_Q[Bb*HH];      // globals @ gw1[640:] + gb1  [96,128]

__device__ __forceinline__ ull pack2(float lo, float hi){
    ull r; asm("mov.b64 %0, {%1, %2};" : "=l"(r) : "f"(lo), "f"(hi)); return r;
}
__device__ __forceinline__ void fma2(ull &d, ull a, ull b){
    asm("fma.rn.f32x2 %0, %1, %2, %0;" : "+l"(d) : "l"(a), "l"(b));
}
__device__ __forceinline__ float2 unpack2(ull v){
    float2 f; asm("mov.b64 {%0, %1}, %2;" : "=f"(f.x), "=f"(f.y) : "l"(v)); return f;
}

// ---------------------------------------------------------------------------
// Precompute part A: A[i*48+t][h] = locals[i,t,:] @ lw1[0:64,h]
// grid (96, 4): each CTA does 12 t-rows; acc[12] -> no spill, 4x parallelism.
// ---------------------------------------------------------------------------
__global__ __launch_bounds__(128) void precompute_a_kernel(
    const float* __restrict__ locals_, const float* __restrict__ lw1)
{
    __shared__ float ltile[12*LD];     // 3 KB

    const int i   = blockIdx.x;
    const int t0  = blockIdx.y * 12;
    const int tid = threadIdx.x;

    for (int idx = tid; idx < 12*LD; idx += 128)
        ltile[idx] = locals_[(i*Tt + t0)*LD + idx];
    __syncthreads();

    const int h = tid;  // 128 threads = 128 output features

    float acc[12];
    #pragma unroll
    for (int t = 0; t < 12; t++) acc[t] = 0.f;
    for (int k = 0; k < LD; k++) {
        float w = lw1[k*HH + h];
        #pragma unroll
        for (int t = 0; t < 12; t++) acc[t] += ltile[t*LD + k] * w;
    }
    #pragma unroll
    for (int t = 0; t < 12; t++) g_A[(i*Tt + t0 + t)*HH + h] = acc[t];
}

// ---------------------------------------------------------------------------
// Precompute part B: Bg, Q, P per batch-row i (same style as passing R1).
// ---------------------------------------------------------------------------
__global__ __launch_bounds__(128) void precompute_pqb_kernel(
    const float* __restrict__ globals_, const float* __restrict__ locals_,
    const float* __restrict__ gw1, const float* __restrict__ gb1,
    const float* __restrict__ lw1, const float* __restrict__ lb1,
    const int* __restrict__ idx_t)
{
    __shared__ float lsrow[MT*LD];     // 2.5 KB
    __shared__ float grow[GD];
    __shared__ int   sidx[MT];

    const int i = blockIdx.x;
    const int tid = threadIdx.x;

    if (tid < GD) grow[tid] = globals_[i*GD + tid];
    if (tid < MT) sidx[tid] = idx_t[i*MT + tid];
    __syncthreads();
    for (int idx = tid; idx < MT*LD; idx += 128) {
        int m = idx >> 6, k = idx & 63;
        lsrow[idx] = locals_[(i*Tt + sidx[m])*LD + k];
    }
    __syncthreads();

    const int h = tid;

    // Bg[i][h] = globals[i] @ lw1[64:, h] + lb1[h]
    float bv = lb1[h];
    for (int k = 0; k < GD; k++) bv += grow[k] * lw1[(LD + k)*HH + h];
    g_Bg[i*HH + h] = bv;

    // Q[i][h] = globals[i] @ gw1[640:, h] + gb1[h]
    float qv = gb1[h];
    for (int k = 0; k < GD; k++) qv += grow[k] * gw1[(MT*LD + k)*HH + h];
    g_Q[i*HH + h] = qv;

    // P[i][h] = lsrow @ gw1[0:640, h]
    float pv = 0.f;
    for (int k = 0; k < MT*LD; k++) pv += lsrow[k] * gw1[k*HH + h];
    g_P[i*HH + h] = pv;
}

// ---------------------------------------------------------------------------
// MI kernel (VERBATIM from passing R1): for each row r and all 96 j:
//   h1 = relu(arow + brows[j]);  h2 = relu(h1 @ w2 + b2);  out = h2 . w3 + b3
// 256 threads: 16 j-groups (6 j each) x 16 h-groups (8 h each = 4+4 split).
// f32x2 packed FMA accumulators (24 per thread).
// ---------------------------------------------------------------------------
__global__ void __launch_bounds__(NT, 1) mi_kernel(
    const float* __restrict__ w2, const float* __restrict__ b2,
    const float* __restrict__ w3, const float* __restrict__ b3,
    float* __restrict__ out, int nrows, int iters, int is_local)
{
    extern __shared__ float sm[];
    float* sw    = sm;                 // [128][128] w2, 64 KB
    float* sh1   = sm + SW_F;          // [96][129]  h1 tile
    float* sarow = sh1 + SH1_F;        // [128]
    float* sw3   = sarow + HH;         // [128]

    const float* arows = is_local ? g_A  : g_P;
    const float* brows = is_local ? g_Bg : g_Q;

    const int tid = threadIdx.x;
    const int jg = tid >> 4;           // 0..15  (2 per warp)
    const int hg = tid & 15;           // 0..15
    const int hA = hg * 4;
    const int hB = 64 + hg * 4;
    const int jb = jg * 6;

    // Load w2, w3 into smem
    const float4* w24 = (const float4*)w2;
    float4* sw4 = (float4*)sw;
    for (int idx = tid; idx < SW_F/4; idx += NT) sw4[idx] = w24[idx];
    if (tid < HH) sw3[tid] = w3[tid];

    // b2 accumulator init (pairs), b3
    float2 q0 = *(const float2*)(b2 + hA);
    float2 q1 = *(const float2*)(b2 + hA + 2);
    float2 q2 = *(const float2*)(b2 + hB);
    float2 q3 = *(const float2*)(b2 + hB + 2);
    ull binit[4] = { pack2(q0.x,q0.y), pack2(q1.x,q1.y), pack2(q2.x,q2.y), pack2(q3.x,q3.y) };
    const float b3v = b3[0];

    for (int r = 0; r < iters; r++) {
        const int row = blockIdx.x * iters + r;
        if (row >= nrows) break;

        __syncthreads();   // prior iter done reading sh1/sarow; first iter: orders sw loads
        if (tid < HH) sarow[tid] = arows[row*HH + tid];
        __syncthreads();

        // h1[j][k] = relu(arow[k] + brows[j][k])
        for (int idx = tid; idx < Bb*HH; idx += NT) {
            int k = idx & 127;
            float v = sarow[k] + brows[idx];
            sh1[(idx >> 7)*SH1_STRIDE + k] = v > 0.f ? v : 0.f;
        }
        __syncthreads();

        ull acc[6][4];
        #pragma unroll
        for (int jj = 0; jj < 6; jj++) {
            #pragma unroll
            for (int p = 0; p < 4; p++) acc[jj][p] = binit[p];
        }

        #pragma unroll 4
        for (int k = 0; k < HH; k++) {
            float4 wa = sw4[(k << 5) + hg];        // w2[k][hA..hA+3]
            float4 wb = sw4[(k << 5) + 16 + hg];   // w2[k][hB..hB+3]
            ull bf0 = pack2(wa.x, wa.y), bf1 = pack2(wa.z, wa.w);
            ull bf2 = pack2(wb.x, wb.y), bf3 = pack2(wb.z, wb.w);
            #pragma unroll
            for (int jj = 0; jj < 6; jj++) {
                float a = sh1[(jb + jj)*SH1_STRIDE + k];
                ull a2 = pack2(a, a);
                fma2(acc[jj][0], a2, bf0);
                fma2(acc[jj][1], a2, bf1);
                fma2(acc[jj][2], a2, bf2);
                fma2(acc[jj][3], a2, bf3);
            }
        }

        // Epilogue: relu(h2) . w3, reduce over 16 hg lanes
        #pragma unroll
        for (int jj = 0; jj < 6; jj++) {
            float2 v0 = unpack2(acc[jj][0]);
            float2 v1 = unpack2(acc[jj][1]);
            float2 v2 = unpack2(acc[jj][2]);
            float2 v3 = unpack2(acc[jj][3]);
            float s = fmaxf(v0.x,0.f)*sw3[hA]   + fmaxf(v0.y,0.f)*sw3[hA+1]
                    + fmaxf(v1.x,0.f)*sw3[hA+2] + fmaxf(v1.y,0.f)*sw3[hA+3]
                    + fmaxf(v2.x,0.f)*sw3[hB]   + fmaxf(v2.y,0.f)*sw3[hB+1]
                    + fmaxf(v3.x,0.f)*sw3[hB+2] + fmaxf(v3.y,0.f)*sw3[hB+3];
            s += __shfl_xor_sync(0xffffffffu, s, 1);
            s += __shfl_xor_sync(0xffffffffu, s, 2);
            s += __shfl_xor_sync(0xffffffffu, s, 4);
            s += __shfl_xor_sync(0xffffffffu, s, 8);
            if (hg == 0) {
                int j = jb + jj;
                int o;
                if (is_local) {
                    int ii = row / Tt, tt = row - ii*Tt;
                    o = tt*(Bb*Bb) + ii*Bb + j;      // locals_mi[t][i][j]
                } else {
                    o = row*Bb + j;                   // globals_mi[i][j]
                }
                out[o] = s + b3v;
            }
        }
    }
}

// ---------------------------------------------------------------------------
extern "C" void kernel_launch(void* const* d_in, const int* in_sizes, int n_in,
                              void* d_out, int out_size)
{
    const float* globals_ = (const float*)d_in[0];
    const float* locals_  = (const float*)d_in[1];
    const float* gw1 = (const float*)d_in[2];
    const float* gb1 = (const float*)d_in[3];
    const float* gw2 = (const float*)d_in[4];
    const float* gb2 = (const float*)d_in[5];
    const float* gw3 = (const float*)d_in[6];
    const float* gb3 = (const float*)d_in[7];
    const float* lw1 = (const float*)d_in[8];
    const float* lb1 = (const float*)d_in[9];
    const float* lw2 = (const float*)d_in[10];
    const float* lb2 = (const float*)d_in[11];
    const float* lw3 = (const float*)d_in[12];
    const float* lb3 = (const float*)d_in[13];
    const int*  idx_t = (const int*)d_in[14];

    float* out = (float*)d_out;

    // Pass-through outputs
    cudaMemcpyAsync(out, globals_, (size_t)Bb*GD*sizeof(float),
                    cudaMemcpyDeviceToDevice, 0);
    cudaMemcpyAsync(out + Bb*GD, locals_, (size_t)Bb*Tt*LD*sizeof(float),
                    cudaMemcpyDeviceToDevice, 0);

    precompute_a_kernel<<<dim3(Bb, 4), 128>>>(locals_, lw1);
    precompute_pqb_kernel<<<Bb, 128>>>(globals_, locals_, gw1, gb1, lw1, lb1, idx_t);

    size_t smem = (size_t)(SW_F + SH1_F + HH + HH) * sizeof(float);
    cudaFuncSetAttribute(mi_kernel, cudaFuncAttributeMaxDynamicSharedMemorySize, (int)smem);

    float* gmi = out + (Bb*GD + Bb*Tt*LD);
    float* lmi = gmi + Bb*Bb;

    // locals path: 4608 rows, 8 rows per CTA (w2 stays resident in smem)
    mi_kernel<<<(Bb*Tt)/8, NT, smem>>>(lw2, lb2, lw3, lb3, lmi, Bb*Tt, 8, 1);
    // globals path: 96 rows
    mi_kernel<<<Bb, NT, smem>>>(gw2, gb2, gw3, gb3, gmi, Bb, 1, 0);
}